// round 1
// baseline (speedup 1.0000x reference)
#include <cuda_runtime.h>
#include <cstdint>

#define NF 128
#define NH 64
#define MAXN 50000
#define MAXE 800000

// Scratch (allocation-free rule: __device__ globals)
__device__ float g_z[(size_t)MAXN * NH];   // 12.8 MB
__device__ float g_sd[MAXN];
__device__ float g_ss[MAXN];
__device__ float g_hsum[MAXN];
__device__ int   g_dst[MAXE];
__device__ int   g_src[MAXE];
__device__ int   g_is32;

// ---------------------------------------------------------------------------
// Zero h_sum + dtype flag
__global__ void zero_kernel(int n_nodes) {
    int i = blockIdx.x * blockDim.x + threadIdx.x;
    if (i < n_nodes) g_hsum[i] = 0.f;
    if (i == 0) g_is32 = 0;
}

// Detect edge_index dtype: scan odd 32-bit words of the first `nelem` words.
// int64 data (values < 2^31) -> high words all zero -> flag stays 0.
// int32 data -> odd words are random indices -> some nonzero -> flag = 1.
__global__ void detect_kernel(const int* __restrict__ w, int nelem) {
    int stride = gridDim.x * blockDim.x;
    int found = 0;
    for (int i = blockIdx.x * blockDim.x + threadIdx.x; i < nelem / 2; i += stride)
        found |= w[2 * i + 1];
    if (found) g_is32 = 1;
}

// Convert edge_index (either dtype) into int32 dst/src arrays.
__global__ void convert_kernel(const void* __restrict__ ei, int E) {
    int i = blockIdx.x * blockDim.x + threadIdx.x;
    if (i >= E) return;
    if (g_is32) {
        const int* p = (const int*)ei;
        g_dst[i] = p[i];
        g_src[i] = p[E + i];
    } else {
        const long long* p = (const long long*)ei;
        g_dst[i] = (int)p[i];
        g_src[i] = (int)p[E + i];
    }
}

// ---------------------------------------------------------------------------
// z = x @ W_fc ; s_dst = z @ a_w[:H] ; s_src = z @ a_w[H:]
// block = (64, 8): 8 rows, 64 output cols. x rows staged in smem; W streamed
// (32 KB, L2/L1 resident). Warp-shuffle + smem reduction for the two scores.
__global__ void __launch_bounds__(512) gemm_kernel(
    const float* __restrict__ x, const float* __restrict__ W,
    const float* __restrict__ aw, int n_nodes)
{
    __shared__ float xs[8][NF];
    __shared__ float red_sd[8][2];
    __shared__ float red_ss[8][2];

    const int c   = threadIdx.x;        // 0..63
    const int ty  = threadIdx.y;        // 0..7
    const int row0 = blockIdx.x * 8;
    const int row  = row0 + ty;
    const int tid  = ty * 64 + c;

    // cooperative load of 8 x-rows (1024 floats)
    for (int i = tid; i < 8 * NF; i += 512) {
        int r = i >> 7, k = i & (NF - 1);
        xs[r][k] = (row0 + r < n_nodes) ? x[(size_t)(row0 + r) * NF + k] : 0.f;
    }
    __syncthreads();

    float acc = 0.f;
#pragma unroll
    for (int k = 0; k < NF; k++)
        acc = fmaf(xs[ty][k], __ldg(&W[k * NH + c]), acc);

    float sd = 0.f, ss = 0.f;
    if (row < n_nodes) {
        g_z[(size_t)row * NH + c] = acc;
        sd = acc * __ldg(&aw[c]);
        ss = acc * __ldg(&aw[NH + c]);
    }
#pragma unroll
    for (int off = 16; off; off >>= 1) {
        sd += __shfl_down_sync(0xffffffffu, sd, off);
        ss += __shfl_down_sync(0xffffffffu, ss, off);
    }
    if ((c & 31) == 0) { red_sd[ty][c >> 5] = sd; red_ss[ty][c >> 5] = ss; }
    __syncthreads();
    if (c == 0 && row < n_nodes) {
        g_sd[row] = red_sd[ty][0] + red_sd[ty][1];
        g_ss[row] = red_ss[ty][0] + red_ss[ty][1];
    }
}

// ---------------------------------------------------------------------------
// Per-edge unnormalized score + segment sum (atomic).
__global__ void edge_score_kernel(const float* __restrict__ ab,
                                  float* __restrict__ alpha, int E)
{
    int e = blockIdx.x * blockDim.x + threadIdx.x;
    if (e >= E) return;
    int d = g_dst[e], s = g_src[e];
    float h = g_sd[d] + g_ss[s] + __ldg(ab);
    h = (h >= 0.f) ? h : 0.05f * h;
    h = expf(h);
    alpha[e] = h;                 // unnormalized; normalized in aggregate pass
    atomicAdd(&g_hsum[d], h);
}

// ---------------------------------------------------------------------------
// alpha_e = h_e / h_sum[dst]; out[dst] += alpha_e * z[src].
// 16 lanes per edge, float4 loads + red.global.add.v4.f32 (sm_90+) to cut
// memory-instruction count 4x vs scalar atomicAdd.
__global__ void __launch_bounds__(256) aggregate_kernel(
    float* __restrict__ out, float* __restrict__ alpha, int E)
{
    int t = blockIdx.x * blockDim.x + threadIdx.x;
    int e = t >> 4;
    int lane = t & 15;
    if (e >= E) return;

    int d = g_dst[e], s = g_src[e];
    float h = alpha[e];                       // all 16 lanes read (broadcast)
    float a = h / g_hsum[d];
    __syncwarp();                             // all reads done before rewrite
    if (lane == 0) alpha[e] = a;              // final normalized alpha output

    float4 zv = *reinterpret_cast<const float4*>(&g_z[(size_t)s * NH + lane * 4]);
    float* p = &out[(size_t)d * NH + lane * 4];
    asm volatile("red.global.add.v4.f32 [%0], {%1,%2,%3,%4};"
                 :: "l"(p), "f"(a * zv.x), "f"(a * zv.y),
                    "f"(a * zv.z), "f"(a * zv.w)
                 : "memory");
}

// ---------------------------------------------------------------------------
extern "C" void kernel_launch(void* const* d_in, const int* in_sizes, int n_in,
                              void* d_out, int out_size)
{
    const float* x  = (const float*)d_in[0];
    const void*  ei = d_in[1];
    const float* W  = (const float*)d_in[2];
    const float* aw = (const float*)d_in[3];
    const float* ab = (const float*)d_in[4];

    const int n_nodes = in_sizes[0] / NF;
    const int E       = in_sizes[1] / 2;

    float* out   = (float*)d_out;
    float* alpha = out + (size_t)n_nodes * NH;

    // zero the aggregation output (poisoned 0xAA by harness)
    cudaMemsetAsync(d_out, 0, (size_t)n_nodes * NH * sizeof(float));

    zero_kernel<<<(n_nodes + 1023) / 1024, 1024>>>(n_nodes);
    detect_kernel<<<256, 256>>>((const int*)ei, in_sizes[1]);
    convert_kernel<<<(E + 255) / 256, 256>>>(ei, E);

    dim3 gb(64, 8);
    gemm_kernel<<<(n_nodes + 7) / 8, gb>>>(x, W, aw, n_nodes);

    edge_score_kernel<<<(E + 255) / 256, 256>>>(ab, alpha, E);

    long long tot = (long long)E * 16;
    aggregate_kernel<<<(int)((tot + 255) / 256), 256>>>(out, alpha, E);
}

// round 2
// speedup vs baseline: 1.5138x; 1.5138x over previous
#include <cuda_runtime.h>
#include <cstdint>

#define NF 128
#define NH 64
#define MAXN 50000
#define MAXE 800000

// Scratch (allocation-free rule: __device__ globals)
__device__ float g_z[(size_t)MAXN * NH];   // 12.8 MB
__device__ float g_sd[MAXN];
__device__ float g_ss[MAXN];
__device__ float g_hsum[MAXN];
__device__ int   g_dst[MAXE];
__device__ int   g_src[MAXE];
__device__ int   g_is32;

// ---------------------------------------------------------------------------
__global__ void zero_kernel(int n_nodes) {
    int i = blockIdx.x * blockDim.x + threadIdx.x;
    if (i < n_nodes) g_hsum[i] = 0.f;
    if (i == 0) g_is32 = 0;
}

// Detect edge_index dtype (int64 from reference vs int32 if canonicalized).
__global__ void detect_kernel(const int* __restrict__ w, int nelem) {
    int stride = gridDim.x * blockDim.x;
    int found = 0;
    for (int i = blockIdx.x * blockDim.x + threadIdx.x; i < nelem / 2; i += stride)
        found |= w[2 * i + 1];
    if (found) g_is32 = 1;
}

__global__ void convert_kernel(const void* __restrict__ ei, int E) {
    int i = blockIdx.x * blockDim.x + threadIdx.x;
    if (i >= E) return;
    if (g_is32) {
        const int* p = (const int*)ei;
        g_dst[i] = p[i];
        g_src[i] = p[E + i];
    } else {
        const long long* p = (const long long*)ei;
        g_dst[i] = (int)p[i];
        g_src[i] = (int)p[E + i];
    }
}

// ---------------------------------------------------------------------------
// Register-tiled GEMM: z = x @ W (64x64 tile per block, 4x4 per thread),
// fused score reduction: s_dst = z @ a_w[:H], s_src = z @ a_w[H:].
// K chunked at 64 so smem = 16KB (x) + 16KB (W).
__global__ void __launch_bounds__(256) gemm_kernel(
    const float* __restrict__ x, const float* __restrict__ W,
    const float* __restrict__ aw, int n_nodes)
{
    __shared__ float xs[64][64];   // [row][k]
    __shared__ float Ws[64][64];   // [k][col]

    const int tid = threadIdx.x;           // 0..255
    const int tx  = tid & 15;              // col group (16)
    const int ty  = tid >> 4;              // row group (16)
    const int row0 = blockIdx.x * 64;

    float acc[4][4];
#pragma unroll
    for (int i = 0; i < 4; i++)
#pragma unroll
        for (int j = 0; j < 4; j++) acc[i][j] = 0.f;

    for (int kc = 0; kc < NF; kc += 64) {
        // load x tile: 64 rows x 64 k = 1024 float4, 4 per thread
#pragma unroll
        for (int it = 0; it < 4; it++) {
            int i = tid + it * 256;
            int r = i >> 4, q = (i & 15) << 2;
            int row = row0 + r;
            float4 v = make_float4(0.f, 0.f, 0.f, 0.f);
            if (row < n_nodes)
                v = *reinterpret_cast<const float4*>(&x[(size_t)row * NF + kc + q]);
            *reinterpret_cast<float4*>(&xs[r][q]) = v;
        }
        // load W tile: 64 k x 64 cols
#pragma unroll
        for (int it = 0; it < 4; it++) {
            int i = tid + it * 256;
            int k = i >> 4, q = (i & 15) << 2;
            *reinterpret_cast<float4*>(&Ws[k][q]) =
                *reinterpret_cast<const float4*>(&W[(size_t)(kc + k) * NH + q]);
        }
        __syncthreads();

#pragma unroll
        for (int k = 0; k < 64; k++) {
            float4 wv = *reinterpret_cast<const float4*>(&Ws[k][tx << 2]);
            float x0 = xs[(ty << 2) + 0][k];
            float x1 = xs[(ty << 2) + 1][k];
            float x2 = xs[(ty << 2) + 2][k];
            float x3 = xs[(ty << 2) + 3][k];
            acc[0][0] = fmaf(x0, wv.x, acc[0][0]); acc[0][1] = fmaf(x0, wv.y, acc[0][1]);
            acc[0][2] = fmaf(x0, wv.z, acc[0][2]); acc[0][3] = fmaf(x0, wv.w, acc[0][3]);
            acc[1][0] = fmaf(x1, wv.x, acc[1][0]); acc[1][1] = fmaf(x1, wv.y, acc[1][1]);
            acc[1][2] = fmaf(x1, wv.z, acc[1][2]); acc[1][3] = fmaf(x1, wv.w, acc[1][3]);
            acc[2][0] = fmaf(x2, wv.x, acc[2][0]); acc[2][1] = fmaf(x2, wv.y, acc[2][1]);
            acc[2][2] = fmaf(x2, wv.z, acc[2][2]); acc[2][3] = fmaf(x2, wv.w, acc[2][3]);
            acc[3][0] = fmaf(x3, wv.x, acc[3][0]); acc[3][1] = fmaf(x3, wv.y, acc[3][1]);
            acc[3][2] = fmaf(x3, wv.z, acc[3][2]); acc[3][3] = fmaf(x3, wv.w, acc[3][3]);
        }
        __syncthreads();
    }

    // scores: per-thread partial over its 4 cols, reduce across tx (width 16)
    const float4 a1 = *reinterpret_cast<const float4*>(&aw[tx << 2]);
    const float4 a2 = *reinterpret_cast<const float4*>(&aw[NH + (tx << 2)]);

#pragma unroll
    for (int i = 0; i < 4; i++) {
        int row = row0 + (ty << 2) + i;
        float sd = acc[i][0] * a1.x + acc[i][1] * a1.y + acc[i][2] * a1.z + acc[i][3] * a1.w;
        float ss = acc[i][0] * a2.x + acc[i][1] * a2.y + acc[i][2] * a2.z + acc[i][3] * a2.w;
#pragma unroll
        for (int off = 8; off; off >>= 1) {
            sd += __shfl_down_sync(0xffffffffu, sd, off, 16);
            ss += __shfl_down_sync(0xffffffffu, ss, off, 16);
        }
        if (row < n_nodes) {
            *reinterpret_cast<float4*>(&g_z[(size_t)row * NH + (tx << 2)]) =
                make_float4(acc[i][0], acc[i][1], acc[i][2], acc[i][3]);
            if (tx == 0) { g_sd[row] = sd; g_ss[row] = ss; }
        }
    }
}

// ---------------------------------------------------------------------------
__global__ void edge_score_kernel(const float* __restrict__ ab,
                                  float* __restrict__ alpha, int E)
{
    int e = blockIdx.x * blockDim.x + threadIdx.x;
    if (e >= E) return;
    int d = g_dst[e], s = g_src[e];
    float h = g_sd[d] + g_ss[s] + __ldg(ab);
    h = (h >= 0.f) ? h : 0.05f * h;
    h = expf(h);
    alpha[e] = h;
    atomicAdd(&g_hsum[d], h);
}

// ---------------------------------------------------------------------------
// alpha_e = h_e / h_sum[dst]; out[dst] += alpha_e * z[src].
__global__ void __launch_bounds__(256) aggregate_kernel(
    float* __restrict__ out, float* __restrict__ alpha, int E)
{
    int t = blockIdx.x * blockDim.x + threadIdx.x;
    int e = t >> 4;
    int lane = t & 15;
    if (e >= E) return;

    int d = g_dst[e], s = g_src[e];
    float h = alpha[e];
    float a = h / g_hsum[d];
    __syncwarp();
    if (lane == 0) alpha[e] = a;

    float4 zv = *reinterpret_cast<const float4*>(&g_z[(size_t)s * NH + lane * 4]);
    float* p = &out[(size_t)d * NH + lane * 4];
    asm volatile("red.global.add.v4.f32 [%0], {%1,%2,%3,%4};"
                 :: "l"(p), "f"(a * zv.x), "f"(a * zv.y),
                    "f"(a * zv.z), "f"(a * zv.w)
                 : "memory");
}

// ---------------------------------------------------------------------------
extern "C" void kernel_launch(void* const* d_in, const int* in_sizes, int n_in,
                              void* d_out, int out_size)
{
    const float* x  = (const float*)d_in[0];
    const void*  ei = d_in[1];
    const float* W  = (const float*)d_in[2];
    const float* aw = (const float*)d_in[3];
    const float* ab = (const float*)d_in[4];

    const int n_nodes = in_sizes[0] / NF;
    const int E       = in_sizes[1] / 2;

    float* out   = (float*)d_out;
    float* alpha = out + (size_t)n_nodes * NH;

    cudaMemsetAsync(d_out, 0, (size_t)n_nodes * NH * sizeof(float));

    zero_kernel<<<(n_nodes + 1023) / 1024, 1024>>>(n_nodes);
    detect_kernel<<<256, 256>>>((const int*)ei, in_sizes[1]);
    convert_kernel<<<(E + 255) / 256, 256>>>(ei, E);

    gemm_kernel<<<(n_nodes + 63) / 64, 256>>>(x, W, aw, n_nodes);

    edge_score_kernel<<<(E + 255) / 256, 256>>>(ab, alpha, E);

    long long tot = (long long)E * 16;
    aggregate_kernel<<<(int)((tot + 255) / 256), 256>>>(out, alpha, E);
}

// round 3
// speedup vs baseline: 1.7902x; 1.1826x over previous
#include <cuda_runtime.h>
#include <cstdint>

#define NF 128
#define NH 64
#define MAXN 50000
#define MAXE 800000

// Scratch (allocation-free rule: __device__ globals)
__device__ float g_z[(size_t)MAXN * NH];   // 12.8 MB
__device__ float g_sd[MAXN];
__device__ float g_ss[MAXN];
__device__ int   g_dst[MAXE];
__device__ int   g_src[MAXE];
__device__ int   g_cnt[MAXN];
__device__ int   g_rowstart[MAXN];
__device__ int   g_cursor[MAXN];
__device__ int   g_bsum[1024];
__device__ int4  g_csr[MAXE];              // {src, eidx, h_bits, 0}
__device__ int   g_is32;

// ---------------------------------------------------------------------------
__global__ void zero_kernel(int n_nodes) {
    int i = blockIdx.x * blockDim.x + threadIdx.x;
    if (i < n_nodes) g_cnt[i] = 0;
    if (i == 0) g_is32 = 0;
}

// Detect edge_index dtype (int64 from reference vs int32 if canonicalized).
__global__ void detect_kernel(const int* __restrict__ w, int nelem) {
    int stride = gridDim.x * blockDim.x;
    int found = 0;
    for (int i = blockIdx.x * blockDim.x + threadIdx.x; i < nelem / 2; i += stride)
        found |= w[2 * i + 1];
    if (found) g_is32 = 1;
}

// Convert to int32 + degree histogram.
__global__ void convert_kernel(const void* __restrict__ ei, int E) {
    int i = blockIdx.x * blockDim.x + threadIdx.x;
    if (i >= E) return;
    int d, s;
    if (g_is32) {
        const int* p = (const int*)ei;
        d = p[i]; s = p[E + i];
    } else {
        const long long* p = (const long long*)ei;
        d = (int)p[i]; s = (int)p[E + i];
    }
    g_dst[i] = d;
    g_src[i] = s;
    atomicAdd(&g_cnt[d], 1);
}

// ---------------------------------------------------------------------------
// Exclusive scan of g_cnt -> g_rowstart (3 small kernels, 256-wide blocks).
__global__ void scanA(int n) {
    __shared__ int s[256];
    int t = threadIdx.x, i = blockIdx.x * 256 + t;
    s[t] = (i < n) ? g_cnt[i] : 0;
    __syncthreads();
    for (int off = 128; off; off >>= 1) {
        if (t < off) s[t] += s[t + off];
        __syncthreads();
    }
    if (t == 0) g_bsum[blockIdx.x] = s[0];
}

__global__ void scanB(int nb) {
    __shared__ int s[256];
    int t = threadIdx.x;
    int v = (t < nb) ? g_bsum[t] : 0;
    s[t] = v; __syncthreads();
    for (int off = 1; off < 256; off <<= 1) {
        int a = (t >= off) ? s[t - off] : 0;
        __syncthreads();
        s[t] += a;
        __syncthreads();
    }
    if (t < nb) g_bsum[t] = s[t] - v;   // exclusive
}

__global__ void scanC(int n) {
    __shared__ int s[256];
    int t = threadIdx.x, i = blockIdx.x * 256 + t;
    int v = (i < n) ? g_cnt[i] : 0;
    s[t] = v; __syncthreads();
    for (int off = 1; off < 256; off <<= 1) {
        int a = (t >= off) ? s[t - off] : 0;
        __syncthreads();
        s[t] += a;
        __syncthreads();
    }
    if (i < n) {
        int start = g_bsum[blockIdx.x] + s[t] - v;
        g_rowstart[i] = start;
        g_cursor[i]   = start;
    }
}

// ---------------------------------------------------------------------------
// Register-tiled GEMM: z = x @ W (64x64 tile per block, 4x4 per thread),
// fused score reduction: s_dst = z @ a_w[:H], s_src = z @ a_w[H:].
__global__ void __launch_bounds__(256) gemm_kernel(
    const float* __restrict__ x, const float* __restrict__ W,
    const float* __restrict__ aw, int n_nodes)
{
    __shared__ float xs[64][64];
    __shared__ float Ws[64][64];

    const int tid = threadIdx.x;
    const int tx  = tid & 15;
    const int ty  = tid >> 4;
    const int row0 = blockIdx.x * 64;

    float acc[4][4];
#pragma unroll
    for (int i = 0; i < 4; i++)
#pragma unroll
        for (int j = 0; j < 4; j++) acc[i][j] = 0.f;

    for (int kc = 0; kc < NF; kc += 64) {
#pragma unroll
        for (int it = 0; it < 4; it++) {
            int i = tid + it * 256;
            int r = i >> 4, q = (i & 15) << 2;
            int row = row0 + r;
            float4 v = make_float4(0.f, 0.f, 0.f, 0.f);
            if (row < n_nodes)
                v = *reinterpret_cast<const float4*>(&x[(size_t)row * NF + kc + q]);
            *reinterpret_cast<float4*>(&xs[r][q]) = v;
        }
#pragma unroll
        for (int it = 0; it < 4; it++) {
            int i = tid + it * 256;
            int k = i >> 4, q = (i & 15) << 2;
            *reinterpret_cast<float4*>(&Ws[k][q]) =
                *reinterpret_cast<const float4*>(&W[(size_t)(kc + k) * NH + q]);
        }
        __syncthreads();

#pragma unroll
        for (int k = 0; k < 64; k++) {
            float4 wv = *reinterpret_cast<const float4*>(&Ws[k][tx << 2]);
            float x0 = xs[(ty << 2) + 0][k];
            float x1 = xs[(ty << 2) + 1][k];
            float x2 = xs[(ty << 2) + 2][k];
            float x3 = xs[(ty << 2) + 3][k];
            acc[0][0] = fmaf(x0, wv.x, acc[0][0]); acc[0][1] = fmaf(x0, wv.y, acc[0][1]);
            acc[0][2] = fmaf(x0, wv.z, acc[0][2]); acc[0][3] = fmaf(x0, wv.w, acc[0][3]);
            acc[1][0] = fmaf(x1, wv.x, acc[1][0]); acc[1][1] = fmaf(x1, wv.y, acc[1][1]);
            acc[1][2] = fmaf(x1, wv.z, acc[1][2]); acc[1][3] = fmaf(x1, wv.w, acc[1][3]);
            acc[2][0] = fmaf(x2, wv.x, acc[2][0]); acc[2][1] = fmaf(x2, wv.y, acc[2][1]);
            acc[2][2] = fmaf(x2, wv.z, acc[2][2]); acc[2][3] = fmaf(x2, wv.w, acc[2][3]);
            acc[3][0] = fmaf(x3, wv.x, acc[3][0]); acc[3][1] = fmaf(x3, wv.y, acc[3][1]);
            acc[3][2] = fmaf(x3, wv.z, acc[3][2]); acc[3][3] = fmaf(x3, wv.w, acc[3][3]);
        }
        __syncthreads();
    }

    const float4 a1 = *reinterpret_cast<const float4*>(&aw[tx << 2]);
    const float4 a2 = *reinterpret_cast<const float4*>(&aw[NH + (tx << 2)]);

#pragma unroll
    for (int i = 0; i < 4; i++) {
        int row = row0 + (ty << 2) + i;
        float sd = acc[i][0] * a1.x + acc[i][1] * a1.y + acc[i][2] * a1.z + acc[i][3] * a1.w;
        float ss = acc[i][0] * a2.x + acc[i][1] * a2.y + acc[i][2] * a2.z + acc[i][3] * a2.w;
#pragma unroll
        for (int off = 8; off; off >>= 1) {
            sd += __shfl_down_sync(0xffffffffu, sd, off, 16);
            ss += __shfl_down_sync(0xffffffffu, ss, off, 16);
        }
        if (row < n_nodes) {
            *reinterpret_cast<float4*>(&g_z[(size_t)row * NH + (tx << 2)]) =
                make_float4(acc[i][0], acc[i][1], acc[i][2], acc[i][3]);
            if (tx == 0) { g_sd[row] = sd; g_ss[row] = ss; }
        }
    }
}

// ---------------------------------------------------------------------------
// Per-edge score + scatter into CSR slot (no hsum atomics needed).
__global__ void edge_scatter_kernel(const float* __restrict__ ab, int E) {
    int e = blockIdx.x * blockDim.x + threadIdx.x;
    if (e >= E) return;
    int d = g_dst[e], s = g_src[e];
    float h = g_sd[d] + g_ss[s] + __ldg(ab);
    h = (h >= 0.f) ? h : 0.05f * h;
    h = expf(h);
    int pos = atomicAdd(&g_cursor[d], 1);
    g_csr[pos] = make_int4(s, e, __float_as_int(h), 0);
}

// ---------------------------------------------------------------------------
// One warp per dst node: accumulate sum(h) and sum(h*z[src]) in registers,
// single write of out row, lane-strided alpha writeback. No atomics.
__global__ void __launch_bounds__(256) aggregate_csr_kernel(
    float* __restrict__ out, float* __restrict__ alpha, int n_nodes)
{
    int w = (blockIdx.x * 256 + threadIdx.x) >> 5;
    int lane = threadIdx.x & 31;
    if (w >= n_nodes) return;

    int start = g_rowstart[w];
    int deg   = g_cnt[w];

    float2 acc = make_float2(0.f, 0.f);
    float hs = 0.f;
    for (int e = 0; e < deg; e++) {
        int4 ent = g_csr[start + e];            // broadcast, 1 sector
        float h = __int_as_float(ent.z);
        hs += h;
        float2 zv = *reinterpret_cast<const float2*>(
            &g_z[(size_t)ent.x * NH + lane * 2]);
        acc.x = fmaf(h, zv.x, acc.x);
        acc.y = fmaf(h, zv.y, acc.y);
    }
    float inv = (hs != 0.f) ? (1.f / hs) : 0.f;
    *reinterpret_cast<float2*>(&out[(size_t)w * NH + lane * 2]) =
        make_float2(acc.x * inv, acc.y * inv);

    for (int e = lane; e < deg; e += 32) {
        int4 ent = g_csr[start + e];            // L1 hit
        alpha[ent.y] = __int_as_float(ent.z) * inv;
    }
}

// ---------------------------------------------------------------------------
extern "C" void kernel_launch(void* const* d_in, const int* in_sizes, int n_in,
                              void* d_out, int out_size)
{
    const float* x  = (const float*)d_in[0];
    const void*  ei = d_in[1];
    const float* W  = (const float*)d_in[2];
    const float* aw = (const float*)d_in[3];
    const float* ab = (const float*)d_in[4];

    const int n_nodes = in_sizes[0] / NF;
    const int E       = in_sizes[1] / 2;
    const int nb      = (n_nodes + 255) / 256;

    float* out   = (float*)d_out;
    float* alpha = out + (size_t)n_nodes * NH;

    zero_kernel<<<(n_nodes + 1023) / 1024, 1024>>>(n_nodes);
    detect_kernel<<<256, 256>>>((const int*)ei, in_sizes[1]);
    convert_kernel<<<(E + 255) / 256, 256>>>(ei, E);

    gemm_kernel<<<(n_nodes + 63) / 64, 256>>>(x, W, aw, n_nodes);

    scanA<<<nb, 256>>>(n_nodes);
    scanB<<<1, 256>>>(nb);
    scanC<<<nb, 256>>>(n_nodes);

    edge_scatter_kernel<<<(E + 255) / 256, 256>>>(ab, E);

    long long tot = (long long)n_nodes * 32;
    aggregate_csr_kernel<<<(int)((tot + 255) / 256), 256>>>(out, alpha, n_nodes);
}